// round 11
// baseline (speedup 1.0000x reference)
#include <cuda_runtime.h>
#include <cstdint>

// Problem constants (fixed by the reference)
#define BB   64
#define MM   2048
#define NN   2048
#define KW   16                      // K in packed 32-bit words (K=64 int8)
#define WORDS (BB * MM * KW)         // packed words per tensor = 2,097,152

#define ROWB 20                      // smem row pitch in words (80B, ldmatrix conflict-free)

// Packed int8 scratch (static device arrays — allowed)
__device__ uint32_t A_pk[WORDS];     // 8.4 MB
__device__ uint32_t B_pk[WORDS];     // 8.4 MB

__device__ __forceinline__ uint32_t pack4(int4 v)
{
    return (uint32_t)(v.x & 0xff)
         | ((uint32_t)(v.y & 0xff) << 8)
         | ((uint32_t)(v.z & 0xff) << 16)
         | ((uint32_t)(v.w)        << 24);
}

// ---------------------------------------------------------------------------
// Fused probe + pack (proven). Each block probes 256 words of `a` for the
// int32-promotion signature, then packs 4 words/thread with uint4 I/O.
// ---------------------------------------------------------------------------
__global__ __launch_bounds__(256)
void pack_kernel(const void* __restrict__ srcA, const void* __restrict__ srcB)
{
    uint32_t v = reinterpret_cast<const uint32_t*>(srcA)[threadIdx.x];
    uint32_t expect = (v & 0x80u) ? 0x00FFFFFFu : 0x00000000u;
    int is_i32 = __syncthreads_and((v >> 8) == expect);

    const int base = (blockIdx.x * blockDim.x + threadIdx.x) * 4;
    if (base >= WORDS) return;

    if (is_i32) {
        const int4* A4 = reinterpret_cast<const int4*>(srcA) + base;
        const int4* B4 = reinterpret_cast<const int4*>(srcB) + base;
        uint4 oa, ob;
        oa.x = pack4(A4[0]); oa.y = pack4(A4[1]); oa.z = pack4(A4[2]); oa.w = pack4(A4[3]);
        ob.x = pack4(B4[0]); ob.y = pack4(B4[1]); ob.z = pack4(B4[2]); ob.w = pack4(B4[3]);
        *reinterpret_cast<uint4*>(&A_pk[base]) = oa;
        *reinterpret_cast<uint4*>(&B_pk[base]) = ob;
    } else {
        *reinterpret_cast<uint4*>(&A_pk[base]) =
            reinterpret_cast<const uint4*>(srcA)[base >> 2];
        *reinterpret_cast<uint4*>(&B_pk[base]) =
            reinterpret_cast<const uint4*>(srcB)[base >> 2];
    }
}

// ---------------------------------------------------------------------------
// Tensor-core GEMM: mma.sync.m16n8k32.s8.
// CTA = 128x64 outputs, 128 threads (4 warps, each 64x32). launch_bounds
// (128,5) clamps regs to ~102 so 5 CTAs/SM stay resident for better
// fill/mma/epilogue phase decorrelation (R10 measured: busy% scales with
// resident CTA count).
// ---------------------------------------------------------------------------
__global__ __launch_bounds__(128, 5)
void bmm_mma_kernel(const float* __restrict__ alpha_p, float* __restrict__ out)
{
    __shared__ uint32_t As[128 * ROWB];   // 10 KB
    __shared__ uint32_t Bs[64 * ROWB];    // 5 KB

    const int bz     = blockIdx.z;
    const int tile_m = blockIdx.y * 128;
    const int tile_n = blockIdx.x * 64;
    const int tid    = threadIdx.x;

    const float alpha = __ldg(alpha_p);

    // ---- Global -> shared: A 128 rows, B 64 rows, 64B each ----
    {
        const uint32_t* __restrict__ Aw = A_pk + (size_t)bz * MM * KW + (size_t)tile_m * KW;
        const uint32_t* __restrict__ Bw = B_pk + (size_t)bz * NN * KW + (size_t)tile_n * KW;
        #pragma unroll
        for (int p = 0; p < 4; p++) {
            const int idx = tid + p * 128;     // 0..511
            const int row = idx >> 2;
            const int q   = idx & 3;
            uint4 va = *reinterpret_cast<const uint4*>(Aw + (size_t)row * KW + q * 4);
            *reinterpret_cast<uint4*>(&As[row * ROWB + q * 4]) = va;
        }
        #pragma unroll
        for (int p = 0; p < 2; p++) {
            const int idx = tid + p * 128;     // 0..255
            const int row = idx >> 2;
            const int q   = idx & 3;
            uint4 vb = *reinterpret_cast<const uint4*>(Bw + (size_t)row * KW + q * 4);
            *reinterpret_cast<uint4*>(&Bs[row * ROWB + q * 4]) = vb;
        }
    }
    __syncthreads();

    const int wid  = tid >> 5;
    const int lane = tid & 31;
    const int g    = lane >> 2;      // row/col group 0..7
    const int t    = lane & 3;
    const int u    = t >> 1;
    const int e    = t & 1;

    const int wm = wid >> 1;         // 0..1 -> m offset (x64)
    const int wn = wid & 1;          // 0..1 -> n offset (x32)

    // ---- ldmatrix lane addresses (verified mapping) ----
    const uint32_t As_u32 = (uint32_t)__cvta_generic_to_shared(As);
    const uint32_t Bs_u32 = (uint32_t)__cvta_generic_to_shared(Bs);

    const int arow = ((lane >> 3) & 1) * 8 + (lane & 7);
    const int akof = (lane >> 4) * 16;
    uint32_t a_addr[4];
    #pragma unroll
    for (int mi = 0; mi < 4; mi++)
        a_addr[mi] = As_u32 + (uint32_t)((wm * 64 + mi * 16 + arow) * (ROWB * 4) + akof);

    const int brow = ((lane >> 4) & 1) * 8 + (lane & 7);
    const int bkof = ((lane >> 3) & 1) * 16;
    uint32_t b_addr[2];
    #pragma unroll
    for (int p = 0; p < 2; p++)
        b_addr[p] = Bs_u32 + (uint32_t)((wn * 32 + p * 16 + brow) * (ROWB * 4) + bkof);

    int c[4][4][4] = {};             // [m16 tile][n8 tile][frag reg]

    #pragma unroll
    for (int s = 0; s < 2; s++) {    // k-step
        uint32_t a[4][4];
        #pragma unroll
        for (int mi = 0; mi < 4; mi++)
            asm volatile("ldmatrix.sync.aligned.m8n8.x4.shared.b16 {%0,%1,%2,%3}, [%4];\n"
                         : "=r"(a[mi][0]), "=r"(a[mi][1]), "=r"(a[mi][2]), "=r"(a[mi][3])
                         : "r"(a_addr[mi] + s * 32));

        uint32_t b[4][2];
        #pragma unroll
        for (int p = 0; p < 2; p++)
            asm volatile("ldmatrix.sync.aligned.m8n8.x4.shared.b16 {%0,%1,%2,%3}, [%4];\n"
                         : "=r"(b[2 * p][0]), "=r"(b[2 * p][1]),
                           "=r"(b[2 * p + 1][0]), "=r"(b[2 * p + 1][1])
                         : "r"(b_addr[p] + s * 32));

        #pragma unroll
        for (int mi = 0; mi < 4; mi++)
            #pragma unroll
            for (int nj = 0; nj < 4; nj++)
                asm volatile(
                    "mma.sync.aligned.m16n8k32.row.col.s32.s8.s8.s32 "
                    "{%0,%1,%2,%3}, {%4,%5,%6,%7}, {%8,%9}, {%0,%1,%2,%3};\n"
                    : "+r"(c[mi][nj][0]), "+r"(c[mi][nj][1]),
                      "+r"(c[mi][nj][2]), "+r"(c[mi][nj][3])
                    : "r"(a[mi][0]), "r"(a[mi][1]), "r"(a[mi][2]), "r"(a[mi][3]),
                      "r"(b[nj][0]), "r"(b[nj][1]));
    }

    // ---- Butterfly epilogue -> direct STG.128 (verified) ----
    // alpha-scale folded directly into shuffle operands to cut live registers.
    const int m_base = tile_m + wm * 64;
    const int n_base = tile_n + wn * 32;
    float* __restrict__ obase = out + (size_t)bz * MM * NN;

    #pragma unroll
    for (int mi = 0; mi < 4; mi++) {
        const int row_lo = m_base + mi * 16 + g;

        #pragma unroll
        for (int p = 0; p < 2; p++) {
            const int njA = 2 * p;
            const int njB = 2 * p + 1;

            // own half (kept) and partner half (sent), both alpha-scaled
            float kA0 = alpha * (float)c[mi][e ? njB : njA][0];
            float kA1 = alpha * (float)c[mi][e ? njB : njA][1];
            float kA2 = alpha * (float)c[mi][e ? njB : njA][2];
            float kA3 = alpha * (float)c[mi][e ? njB : njA][3];
            float s0  = alpha * (float)c[mi][e ? njA : njB][0];
            float s1  = alpha * (float)c[mi][e ? njA : njB][1];
            float s2  = alpha * (float)c[mi][e ? njA : njB][2];
            float s3  = alpha * (float)c[mi][e ? njA : njB][3];

            float r0 = __shfl_xor_sync(0xFFFFFFFFu, s0, 1);
            float r1 = __shfl_xor_sync(0xFFFFFFFFu, s1, 1);
            float r2 = __shfl_xor_sync(0xFFFFFFFFu, s2, 1);
            float r3 = __shfl_xor_sync(0xFFFFFFFFu, s3, 1);

            float4 vlo, vhi;
            if (e == 0) {
                vlo = make_float4(kA0, kA1, r0, r1);
                vhi = make_float4(kA2, kA3, r2, r3);
            } else {
                vlo = make_float4(r0, r1, kA0, kA1);
                vhi = make_float4(r2, r3, kA2, kA3);
            }

            const int col = n_base + 16 * p + 8 * e + 4 * u;
            *reinterpret_cast<float4*>(obase + (size_t)row_lo * NN + col)       = vlo;
            *reinterpret_cast<float4*>(obase + (size_t)(row_lo + 8) * NN + col) = vhi;
        }
    }
}

extern "C" void kernel_launch(void* const* d_in, const int* in_sizes, int n_in,
                              void* d_out, int out_size)
{
    // alpha is the unique 1-element input; the two big tensors are a then b.
    int ia = -1, ib = -1, ialpha = -1;
    for (int i = 0; i < n_in; i++) {
        if (in_sizes[i] == 1) {
            if (ialpha < 0) ialpha = i;
        } else if (ia < 0) {
            ia = i;
        } else if (ib < 0) {
            ib = i;
        }
    }
    if (ialpha < 0) ialpha = n_in - 1;

    const void*  a     = d_in[ia];
    const void*  b     = d_in[ib];
    const float* alpha = reinterpret_cast<const float*>(d_in[ialpha]);
    float*       out   = reinterpret_cast<float*>(d_out);

    pack_kernel<<<WORDS / (256 * 4), 256>>>(a, b);

    dim3 grid(NN / 64, MM / 128, BB);   // (32, 16, 64) = 32768 CTAs
    bmm_mma_kernel<<<grid, 128>>>(alpha, out);
}

// round 12
// speedup vs baseline: 1.2530x; 1.2530x over previous
#include <cuda_runtime.h>
#include <cstdint>

// Problem constants (fixed by the reference)
#define BB   64
#define MM   2048
#define NN   2048
#define KW   16                      // K in packed 32-bit words (K=64 int8)
#define WORDS (BB * MM * KW)         // packed words per tensor = 2,097,152

#define ROWB 20                      // smem row pitch in words (80B, ldmatrix conflict-free)

// Packed int8 scratch (static device arrays — allowed)
__device__ uint32_t A_pk[WORDS];     // 8.4 MB
__device__ uint32_t B_pk[WORDS];     // 8.4 MB

__device__ __forceinline__ uint32_t pack4(int4 v)
{
    return (uint32_t)(v.x & 0xff)
         | ((uint32_t)(v.y & 0xff) << 8)
         | ((uint32_t)(v.z & 0xff) << 16)
         | ((uint32_t)(v.w)        << 24);
}

// ---------------------------------------------------------------------------
// Fused probe + pack (proven R7-R10). Each block probes 256 words of `a` for
// the int32-promotion signature, then packs 4 words/thread with uint4 I/O.
// ---------------------------------------------------------------------------
__global__ __launch_bounds__(256)
void pack_kernel(const void* __restrict__ srcA, const void* __restrict__ srcB)
{
    uint32_t v = reinterpret_cast<const uint32_t*>(srcA)[threadIdx.x];
    uint32_t expect = (v & 0x80u) ? 0x00FFFFFFu : 0x00000000u;
    int is_i32 = __syncthreads_and((v >> 8) == expect);

    const int base = (blockIdx.x * blockDim.x + threadIdx.x) * 4;
    if (base >= WORDS) return;

    if (is_i32) {
        const int4* A4 = reinterpret_cast<const int4*>(srcA) + base;
        const int4* B4 = reinterpret_cast<const int4*>(srcB) + base;
        uint4 oa, ob;
        oa.x = pack4(A4[0]); oa.y = pack4(A4[1]); oa.z = pack4(A4[2]); oa.w = pack4(A4[3]);
        ob.x = pack4(B4[0]); ob.y = pack4(B4[1]); ob.z = pack4(B4[2]); ob.w = pack4(B4[3]);
        *reinterpret_cast<uint4*>(&A_pk[base]) = oa;
        *reinterpret_cast<uint4*>(&B_pk[base]) = ob;
    } else {
        *reinterpret_cast<uint4*>(&A_pk[base]) =
            reinterpret_cast<const uint4*>(srcA)[base >> 2];
        *reinterpret_cast<uint4*>(&B_pk[base]) =
            reinterpret_cast<const uint4*>(srcB)[base >> 2];
    }
}

// ---------------------------------------------------------------------------
// Tensor-core GEMM: mma.sync.m16n8k32.s8.
// CTA = 128x64 outputs, 128 threads (4 warps, each 64x32) -> 4 CTAs/SM for
// phase-decorrelated fill/mma/epilogue overlap. R10 configuration: measured
// optimum (R9: 2 big CTAs regressed; R11: reg-clamped 5 CTAs spilled).
// ---------------------------------------------------------------------------
__global__ __launch_bounds__(128, 4)
void bmm_mma_kernel(const float* __restrict__ alpha_p, float* __restrict__ out)
{
    __shared__ uint32_t As[128 * ROWB];   // 10 KB
    __shared__ uint32_t Bs[64 * ROWB];    // 5 KB

    const int bz     = blockIdx.z;
    const int tile_m = blockIdx.y * 128;
    const int tile_n = blockIdx.x * 64;
    const int tid    = threadIdx.x;

    // ---- Global -> shared: A 128 rows, B 64 rows, 64B each ----
    {
        const uint32_t* __restrict__ Aw = A_pk + (size_t)bz * MM * KW + (size_t)tile_m * KW;
        const uint32_t* __restrict__ Bw = B_pk + (size_t)bz * NN * KW + (size_t)tile_n * KW;
        #pragma unroll
        for (int p = 0; p < 4; p++) {
            const int idx = tid + p * 128;     // 0..511
            const int row = idx >> 2;
            const int q   = idx & 3;
            uint4 va = *reinterpret_cast<const uint4*>(Aw + (size_t)row * KW + q * 4);
            *reinterpret_cast<uint4*>(&As[row * ROWB + q * 4]) = va;
        }
        #pragma unroll
        for (int p = 0; p < 2; p++) {
            const int idx = tid + p * 128;     // 0..255
            const int row = idx >> 2;
            const int q   = idx & 3;
            uint4 vb = *reinterpret_cast<const uint4*>(Bw + (size_t)row * KW + q * 4);
            *reinterpret_cast<uint4*>(&Bs[row * ROWB + q * 4]) = vb;
        }
    }
    __syncthreads();

    const int wid  = tid >> 5;
    const int lane = tid & 31;
    const int g    = lane >> 2;      // row/col group 0..7
    const int t    = lane & 3;
    const int u    = t >> 1;
    const int e    = t & 1;

    const int wm = wid >> 1;         // 0..1 -> m offset (x64)
    const int wn = wid & 1;          // 0..1 -> n offset (x32)

    // ---- ldmatrix lane addresses (verified mapping) ----
    const uint32_t As_u32 = (uint32_t)__cvta_generic_to_shared(As);
    const uint32_t Bs_u32 = (uint32_t)__cvta_generic_to_shared(Bs);

    const int arow = ((lane >> 3) & 1) * 8 + (lane & 7);
    const int akof = (lane >> 4) * 16;
    uint32_t a_addr[4];
    #pragma unroll
    for (int mi = 0; mi < 4; mi++)
        a_addr[mi] = As_u32 + (uint32_t)((wm * 64 + mi * 16 + arow) * (ROWB * 4) + akof);

    const int brow = ((lane >> 4) & 1) * 8 + (lane & 7);
    const int bkof = ((lane >> 3) & 1) * 16;
    uint32_t b_addr[2];
    #pragma unroll
    for (int p = 0; p < 2; p++)
        b_addr[p] = Bs_u32 + (uint32_t)((wn * 32 + p * 16 + brow) * (ROWB * 4) + bkof);

    int c[4][4][4] = {};             // [m16 tile][n8 tile][frag reg]

    #pragma unroll
    for (int s = 0; s < 2; s++) {    // k-step
        uint32_t a[4][4];
        #pragma unroll
        for (int mi = 0; mi < 4; mi++)
            asm volatile("ldmatrix.sync.aligned.m8n8.x4.shared.b16 {%0,%1,%2,%3}, [%4];\n"
                         : "=r"(a[mi][0]), "=r"(a[mi][1]), "=r"(a[mi][2]), "=r"(a[mi][3])
                         : "r"(a_addr[mi] + s * 32));

        uint32_t b[4][2];
        #pragma unroll
        for (int p = 0; p < 2; p++)
            asm volatile("ldmatrix.sync.aligned.m8n8.x4.shared.b16 {%0,%1,%2,%3}, [%4];\n"
                         : "=r"(b[2 * p][0]), "=r"(b[2 * p][1]),
                           "=r"(b[2 * p + 1][0]), "=r"(b[2 * p + 1][1])
                         : "r"(b_addr[p] + s * 32));

        #pragma unroll
        for (int mi = 0; mi < 4; mi++)
            #pragma unroll
            for (int nj = 0; nj < 4; nj++)
                asm volatile(
                    "mma.sync.aligned.m16n8k32.row.col.s32.s8.s8.s32 "
                    "{%0,%1,%2,%3}, {%4,%5,%6,%7}, {%8,%9}, {%0,%1,%2,%3};\n"
                    : "+r"(c[mi][nj][0]), "+r"(c[mi][nj][1]),
                      "+r"(c[mi][nj][2]), "+r"(c[mi][nj][3])
                    : "r"(a[mi][0]), "r"(a[mi][1]), "r"(a[mi][2]), "r"(a[mi][3]),
                      "r"(b[nj][0]), "r"(b[nj][1]));
    }

    // ---- Butterfly epilogue -> direct STG.128 (verified R7/R10) ----
    const float alpha = __ldg(alpha_p);
    const int m_base = tile_m + wm * 64;
    const int n_base = tile_n + wn * 32;
    float* __restrict__ obase = out + (size_t)bz * MM * NN;

    #pragma unroll
    for (int mi = 0; mi < 4; mi++) {
        float f[4][4];
        #pragma unroll
        for (int nj = 0; nj < 4; nj++)
            #pragma unroll
            for (int r = 0; r < 4; r++)
                f[nj][r] = alpha * (float)c[mi][nj][r];

        const int row_lo = m_base + mi * 16 + g;

        #pragma unroll
        for (int p = 0; p < 2; p++) {
            const int njA = 2 * p;
            const int njB = 2 * p + 1;

            float s0 = e ? f[njA][0] : f[njB][0];
            float s1 = e ? f[njA][1] : f[njB][1];
            float s2 = e ? f[njA][2] : f[njB][2];
            float s3 = e ? f[njA][3] : f[njB][3];
            float r0 = __shfl_xor_sync(0xFFFFFFFFu, s0, 1);
            float r1 = __shfl_xor_sync(0xFFFFFFFFu, s1, 1);
            float r2 = __shfl_xor_sync(0xFFFFFFFFu, s2, 1);
            float r3 = __shfl_xor_sync(0xFFFFFFFFu, s3, 1);

            float4 vlo, vhi;
            if (e == 0) {
                vlo = make_float4(f[njA][0], f[njA][1], r0, r1);
                vhi = make_float4(f[njA][2], f[njA][3], r2, r3);
            } else {
                vlo = make_float4(r0, r1, f[njB][0], f[njB][1]);
                vhi = make_float4(r2, r3, f[njB][2], f[njB][3]);
            }

            const int col = n_base + 16 * p + 8 * e + 4 * u;
            *reinterpret_cast<float4*>(obase + (size_t)row_lo * NN + col)       = vlo;
            *reinterpret_cast<float4*>(obase + (size_t)(row_lo + 8) * NN + col) = vhi;
        }
    }
}

extern "C" void kernel_launch(void* const* d_in, const int* in_sizes, int n_in,
                              void* d_out, int out_size)
{
    // alpha is the unique 1-element input; the two big tensors are a then b.
    int ia = -1, ib = -1, ialpha = -1;
    for (int i = 0; i < n_in; i++) {
        if (in_sizes[i] == 1) {
            if (ialpha < 0) ialpha = i;
        } else if (ia < 0) {
            ia = i;
        } else if (ib < 0) {
            ib = i;
        }
    }
    if (ialpha < 0) ialpha = n_in - 1;

    const void*  a     = d_in[ia];
    const void*  b     = d_in[ib];
    const float* alpha = reinterpret_cast<const float*>(d_in[ialpha]);
    float*       out   = reinterpret_cast<float*>(d_out);

    pack_kernel<<<WORDS / (256 * 4), 256>>>(a, b);

    dim3 grid(NN / 64, MM / 128, BB);   // (32, 16, 64) = 32768 CTAs
    bmm_mma_kernel<<<grid, 128>>>(alpha, out);
}